// round 14
// baseline (speedup 1.0000x reference)
#include <cuda_runtime.h>
#include <cuda_fp16.h>
#include <math.h>
#include <stdint.h>

// Problem constants
#define MTOT   80000
#define NBATCH 2
#define NPB    40000
#define DIN    1024
#define LDIM   512
#define DDIM   384
#define NDT    6
#define NCHUNK 157
#define NBAND  625     // m-bands of 128 rows

// Scratch (device globals)
__device__ __align__(16) __half g_xh[(size_t)MTOT * DIN];   // x fp16 (rne)
__device__ __align__(16) __half g_hh[(size_t)MTOT * LDIM];  // h fp16 (gemm2 A + pool)
__device__ __align__(16) __half g_Wfh[LDIM * DIN];          // Wf^T [n][k] fp16
__device__ __align__(16) __half g_Wah[DDIM * LDIM];         // Wa^T [d][k] fp16
__device__ __align__(16) __half g_Wbh[DDIM * LDIM];         // Wb^T [d][k] fp16
__device__ float g_spart[(size_t)NDT * MTOT];
__device__ __align__(16) float g_Upart[(size_t)NBATCH * NCHUNK * LDIM];
__device__ float g_Zpart[NBATCH * NCHUNK];
__device__ volatile int g_bflag[NBAND];   // per-band x-converted flags (reset by final_kernel)

// ---------------------------------------------------------------------------
// Helpers
// ---------------------------------------------------------------------------
__device__ __forceinline__ uint32_t smem_u32(const void* p) {
    uint32_t a;
    asm("{ .reg .u64 t; cvta.to.shared.u64 t, %1; cvt.u32.u64 %0, t; }"
        : "=r"(a) : "l"(p));
    return a;
}
__device__ __forceinline__ void cp16(uint32_t dst, const void* src) {
    asm volatile("cp.async.cg.shared.global [%0], [%1], 16;" :: "r"(dst), "l"(src));
}
#define CP_COMMIT() asm volatile("cp.async.commit_group;")
#define CP_WAIT1()  asm volatile("cp.async.wait_group 1;")

__device__ __forceinline__ void ldsm4(uint32_t* r, uint32_t addr) {
    asm volatile("ldmatrix.sync.aligned.m8n8.x4.shared.b16 {%0,%1,%2,%3}, [%4];"
                 : "=r"(r[0]), "=r"(r[1]), "=r"(r[2]), "=r"(r[3]) : "r"(addr));
}
__device__ __forceinline__ void mma16(float* c, const uint32_t* a,
                                      uint32_t b0, uint32_t b1) {
    asm volatile(
        "mma.sync.aligned.m16n8k16.row.col.f32.f16.f16.f32 "
        "{%0,%1,%2,%3},{%4,%5,%6,%7},{%8,%9},{%0,%1,%2,%3};"
        : "+f"(c[0]), "+f"(c[1]), "+f"(c[2]), "+f"(c[3])
        : "r"(a[0]), "r"(a[1]), "r"(a[2]), "r"(a[3]), "r"(b0), "r"(b1));
}
__device__ __forceinline__ float tanh_fast(float x) {
    float r;
    asm("tanh.approx.f32 %0, %1;" : "=f"(r) : "f"(x));
    return r;
}
__device__ __forceinline__ float sigmoid_fast(float x) {
    float e, r;
    asm("ex2.approx.f32 %0, %1;" : "=f"(e) : "f"(-x * 1.4426950408889634f));
    asm("rcp.approx.f32 %0, %1;" : "=f"(r) : "f"(1.0f + e));
    return r;
}

// ---------------------------------------------------------------------------
// Weight prep: transpose to K-major [n][k] + fp16(rne)
// ---------------------------------------------------------------------------
__global__ void prep_w(const float* __restrict__ Wf,
                       const float* __restrict__ Wa,
                       const float* __restrict__ Wb)
{
    int idx = blockIdx.x * 256 + threadIdx.x;
    if (idx < LDIM * DIN) {
        int n = idx >> 10, k = idx & 1023;
        g_Wfh[idx] = __float2half_rn(Wf[k * LDIM + n]);
    }
    if (idx < DDIM * LDIM) {
        int d = idx >> 9, k = idx & 511;
        g_Wah[idx] = __float2half_rn(Wa[k * DDIM + d]);
        g_Wbh[idx] = __float2half_rn(Wb[k * DDIM + d]);
    }
}

// ---------------------------------------------------------------------------
// GEMM1 (fp16 mma m16n8k16): h = relu(x @ Wf + bf). CTA 128x128, k-stage 64,
// 3-stage cp.async ring. 8 warps (2m x 4n), warp tile 64x32.
// FUSED x-conversion: the bx==0 CTA of each m-band converts that band's x
// (fp32 -> fp16 rne) into g_xh, then sets the band flag; sibling CTAs
// (dispatched later by bid order -> no deadlock) spin on the flag.
// Mainloop byte-identical to the R10/R13 winner.
// ---------------------------------------------------------------------------
#define G1_BOFF  18432
#define G1_STAGE 36864
#define G1_SMEM  (3 * G1_STAGE)

__global__ void __launch_bounds__(256, 2) gemm1_mma(
    const float* __restrict__ x, const float* __restrict__ bfp)
{
    extern __shared__ char smch[];
    const uint32_t sb = smem_u32(smch);
    const int tid  = threadIdx.x;
    const int warp = tid >> 5, lane = tid & 31;
    const int gr = lane >> 2, tg = lane & 3;
    const int n0 = blockIdx.x * 128;
    const int m0 = blockIdx.y * 128;
    const int wm = (warp >> 2) * 64, wn = (warp & 3) * 32;

    // ---- fused x-conversion phase ----
    if (blockIdx.x == 0) {
        // convert this band: 128 rows x 1024 cols fp32 -> fp16, 16384 chunks of 8
        const float4* src = (const float4*)(x + (size_t)m0 * DIN);
        uint4* dst = (uint4*)(g_xh + (size_t)m0 * DIN);
        for (int c = tid; c < 16384; c += 256) {
            float4 v0 = src[2 * c];
            float4 v1 = src[2 * c + 1];
            __half2 h0 = __floats2half2_rn(v0.x, v0.y);
            __half2 h1 = __floats2half2_rn(v0.z, v0.w);
            __half2 h2 = __floats2half2_rn(v1.x, v1.y);
            __half2 h3 = __floats2half2_rn(v1.z, v1.w);
            uint4 u;
            u.x = *(uint32_t*)&h0; u.y = *(uint32_t*)&h1;
            u.z = *(uint32_t*)&h2; u.w = *(uint32_t*)&h3;
            dst[c] = u;
        }
        __syncthreads();
        if (tid == 0) {
            __threadfence();
            g_bflag[blockIdx.y] = 1;
        }
    } else {
        if (tid == 0) {
            while (g_bflag[blockIdx.y] == 0) __nanosleep(64);
            __threadfence();
        }
        __syncthreads();
    }

    auto issue = [&](int ks, int st) {
        const uint32_t base = sb + st * G1_STAGE;
#pragma unroll
        for (int i = 0; i < 4; i++) {
            int idx = tid + i * 256;
            int row = idx >> 3, c8 = idx & 7;
            cp16(base + row * 144 + c8 * 16,
                 g_xh + (size_t)(m0 + row) * DIN + ks * 64 + c8 * 8);
        }
#pragma unroll
        for (int i = 0; i < 4; i++) {
            int idx = tid + i * 256;
            int row = idx >> 3, c8 = idx & 7;
            cp16(base + G1_BOFF + row * 144 + c8 * 16,
                 g_Wfh + (size_t)(n0 + row) * DIN + ks * 64 + c8 * 8);
        }
    };

    const uint32_t laneA = (uint32_t)(((lane & 7) + ((lane >> 3) & 1) * 8) * 144
                                      + ((lane >> 4) & 1) * 16);
    const uint32_t laneB = (uint32_t)(((lane & 7) + ((lane >> 4) & 1) * 8) * 144
                                      + ((lane >> 3) & 1) * 16);

    float acc[4][4][4];
#pragma unroll
    for (int a = 0; a < 4; a++)
#pragma unroll
        for (int b = 0; b < 4; b++)
#pragma unroll
            for (int c = 0; c < 4; c++) acc[a][b][c] = 0.f;

    issue(0, 0); CP_COMMIT();
    issue(1, 1); CP_COMMIT();

    for (int ks = 0; ks < 16; ks++) {
        CP_WAIT1();
        __syncthreads();
        if (ks + 2 < 16) issue(ks + 2, (ks + 2) % 3);
        CP_COMMIT();
        const uint32_t sA = sb + (ks % 3) * G1_STAGE;
        const uint32_t sB = sA + G1_BOFF;
#pragma unroll
        for (int kk = 0; kk < 4; kk++) {
            const uint32_t ko = kk * 32;   // 16 fp16 = 32 B
            uint32_t af[4][4];
#pragma unroll
            for (int mf = 0; mf < 4; mf++)
                ldsm4(af[mf], sA + (wm + mf * 16) * 144 + ko + laneA);
            uint32_t bf[2][4];
#pragma unroll
            for (int p = 0; p < 2; p++)
                ldsm4(bf[p], sB + (wn + p * 16) * 144 + ko + laneB);
#pragma unroll
            for (int mf = 0; mf < 4; mf++)
#pragma unroll
                for (int nf = 0; nf < 4; nf++) {
                    const int p = nf >> 1;
                    mma16(acc[mf][nf], af[mf],
                          bf[p][(nf & 1) * 2], bf[p][(nf & 1) * 2 + 1]);
                }
        }
    }

    // Epilogue: bias + relu, store fp16 only
#pragma unroll
    for (int mf = 0; mf < 4; mf++) {
        const int r0 = m0 + wm + mf * 16 + gr;
#pragma unroll
        for (int nf = 0; nf < 4; nf++) {
            const int n = n0 + wn + nf * 8 + 2 * tg;
            const float b0v = bfp[n], b1v = bfp[n + 1];
            ((__half2*)g_hh)[((size_t)r0 * LDIM + n) >> 1] =
                __floats2half2_rn(fmaxf(acc[mf][nf][0] + b0v, 0.f),
                                  fmaxf(acc[mf][nf][1] + b1v, 0.f));
            ((__half2*)g_hh)[((size_t)(r0 + 8) * LDIM + n) >> 1] =
                __floats2half2_rn(fmaxf(acc[mf][nf][2] + b0v, 0.f),
                                  fmaxf(acc[mf][nf][3] + b1v, 0.f));
        }
    }
}

// ---------------------------------------------------------------------------
// GEMM2 (fp16, fused): per (d-tile 64, m-tile 128): acca = h@Wa, accg = h@Wb,
// spart[row] = sum_d tanh(acca+ba)*sigmoid(accg+bb)*wc.
// 8 warps (4m x 2d), warp tile 32m x 32d, dual accumulators. k-stage 64.
// (R9 winner config, byte-identical)
// ---------------------------------------------------------------------------
#define G2_BAOFF 18432
#define G2_BBOFF 27648
#define G2_STAGE 36864
#define G2_SMEM  (3 * G2_STAGE)

__global__ void __launch_bounds__(256, 2) gemm2_mma(
    const float* __restrict__ ba, const float* __restrict__ bb,
    const float* __restrict__ Wc)
{
    extern __shared__ char smch[];
    __shared__ float red[256];
    const uint32_t sb = smem_u32(smch);
    const int tid  = threadIdx.x;
    const int warp = tid >> 5, lane = tid & 31;
    const int gr = lane >> 2, tg = lane & 3;
    const int n0 = blockIdx.x * 64;
    const int m0 = blockIdx.y * 128;
    const int wm = (warp >> 1) * 32;   // m quarter
    const int wd = (warp & 1) * 32;    // d half

    const uint32_t laneA = (uint32_t)(((lane & 7) + ((lane >> 3) & 1) * 8) * 144
                                      + ((lane >> 4) & 1) * 16);
    const uint32_t laneB = (uint32_t)(((lane & 7) + ((lane >> 4) & 1) * 8) * 144
                                      + ((lane >> 3) & 1) * 16);

    auto issue = [&](int ks, int st) {
        const uint32_t base = sb + st * G2_STAGE;
#pragma unroll
        for (int i = 0; i < 4; i++) {
            int idx = tid + i * 256;
            int row = idx >> 3, c8 = idx & 7;
            cp16(base + row * 144 + c8 * 16,
                 g_hh + (size_t)(m0 + row) * LDIM + ks * 64 + c8 * 8);
        }
#pragma unroll
        for (int i = 0; i < 2; i++) {
            int idx = tid + i * 256;
            int row = idx >> 3, c8 = idx & 7;
            cp16(base + G2_BAOFF + row * 144 + c8 * 16,
                 g_Wah + (size_t)(n0 + row) * LDIM + ks * 64 + c8 * 8);
        }
#pragma unroll
        for (int i = 0; i < 2; i++) {
            int idx = tid + i * 256;
            int row = idx >> 3, c8 = idx & 7;
            cp16(base + G2_BBOFF + row * 144 + c8 * 16,
                 g_Wbh + (size_t)(n0 + row) * LDIM + ks * 64 + c8 * 8);
        }
    };

    float acca[2][4][4], accg[2][4][4];
#pragma unroll
    for (int a = 0; a < 2; a++)
#pragma unroll
        for (int b = 0; b < 4; b++)
#pragma unroll
            for (int c = 0; c < 4; c++) { acca[a][b][c] = 0.f; accg[a][b][c] = 0.f; }

    issue(0, 0); CP_COMMIT();
    issue(1, 1); CP_COMMIT();

    for (int ks = 0; ks < 8; ks++) {
        CP_WAIT1();
        __syncthreads();
        if (ks + 2 < 8) issue(ks + 2, (ks + 2) % 3);
        CP_COMMIT();
        const uint32_t sA  = sb + (ks % 3) * G2_STAGE;
        const uint32_t sBa = sA + G2_BAOFF;
        const uint32_t sBb = sA + G2_BBOFF;
#pragma unroll
        for (int kk = 0; kk < 4; kk++) {
            const uint32_t ko = kk * 32;
            uint32_t af[2][4];
#pragma unroll
            for (int mf = 0; mf < 2; mf++)
                ldsm4(af[mf], sA + (wm + mf * 16) * 144 + ko + laneA);
            uint32_t bfa[2][4], bfb[2][4];
#pragma unroll
            for (int p = 0; p < 2; p++) {
                ldsm4(bfa[p], sBa + (wd + p * 16) * 144 + ko + laneB);
                ldsm4(bfb[p], sBb + (wd + p * 16) * 144 + ko + laneB);
            }
#pragma unroll
            for (int mf = 0; mf < 2; mf++)
#pragma unroll
                for (int nf = 0; nf < 4; nf++) {
                    const int p = nf >> 1;
                    mma16(acca[mf][nf], af[mf],
                          bfa[p][(nf & 1) * 2], bfa[p][(nf & 1) * 2 + 1]);
                    mma16(accg[mf][nf], af[mf],
                          bfb[p][(nf & 1) * 2], bfb[p][(nf & 1) * 2 + 1]);
                }
        }
    }

    // Epilogue: tanh*sigmoid*wc, warp-local reduce over its 32 d-cols
    float bav[4][2], bbv[4][2], wcv[4][2];
#pragma unroll
    for (int nf = 0; nf < 4; nf++) {
        const int d = n0 + wd + nf * 8 + 2 * tg;
        bav[nf][0] = ba[d]; bav[nf][1] = ba[d + 1];
        bbv[nf][0] = bb[d]; bbv[nf][1] = bb[d + 1];
        wcv[nf][0] = Wc[d]; wcv[nf][1] = Wc[d + 1];
    }
#pragma unroll
    for (int mf = 0; mf < 2; mf++) {
#pragma unroll
        for (int rh = 0; rh < 2; rh++) {
            float s = 0.f;
#pragma unroll
            for (int nf = 0; nf < 4; nf++) {
#pragma unroll
                for (int c = 0; c < 2; c++) {
                    const float av = tanh_fast(acca[mf][nf][rh * 2 + c] + bav[nf][c]);
                    const float gv = sigmoid_fast(accg[mf][nf][rh * 2 + c] + bbv[nf][c]);
                    s = fmaf(av * gv, wcv[nf][c], s);
                }
            }
            s += __shfl_xor_sync(0xFFFFFFFF, s, 1);
            s += __shfl_xor_sync(0xFFFFFFFF, s, 2);
            if (tg == 0)
                red[(warp & 1) * 128 + wm + mf * 16 + rh * 8 + gr] = s;
        }
    }
    __syncthreads();
    if (tid < 128)
        g_spart[(size_t)blockIdx.x * MTOT + m0 + tid] = red[tid] + red[128 + tid];
}

// ---------------------------------------------------------------------------
// Pool (fused scores): e = exp(bc + sum spart)  [no max pass: |s| <= sum|wc|
// ~ 17, exp safe in fp32];  Upart[l] = sum_n e_n * h[n][l];  Zpart = sum e.
// ---------------------------------------------------------------------------
__global__ void __launch_bounds__(256) pool_kernel(const float* __restrict__ bc)
{
    __shared__ float esh[256];
    __shared__ float zr[256];
    const int b = blockIdx.y, cx = blockIdx.x, tid = threadIdx.x;
    const int base = cx * 256;
    const int n = base + tid;
    float e = 0.f;
    if (n < NPB) {
        const int gm = b * NPB + n;
        float s = bc[0];
#pragma unroll
        for (int t = 0; t < NDT; t++) s += g_spart[(size_t)t * MTOT + gm];
        e = expf(s);
    }
    esh[tid] = e;
    zr[tid]  = e;
    __syncthreads();
    for (int o = 128; o > 0; o >>= 1) {
        if (tid < o) zr[tid] += zr[tid + o];
        __syncthreads();
    }
    if (tid == 0) g_Zpart[b * NCHUNK + cx] = zr[0];

    const int rmax = min(256, NPB - base);
    const int c = tid * 2;
    const __half* hb = g_hh + ((size_t)b * NPB + base) * LDIM + c;
    float ax = 0.f, ay = 0.f;
    for (int r = 0; r < rmax; r++) {
        const float w = esh[r];
        float2 hv = __half22float2(*(const __half2*)(hb + (size_t)r * LDIM));
        ax = fmaf(w, hv.x, ax);
        ay = fmaf(w, hv.y, ay);
    }
    float* up = g_Upart + (size_t)(b * NCHUNK + cx) * LDIM + c;
    up[0] = ax;
    up[1] = ay;
}

// ---------------------------------------------------------------------------
// Final reduce + classifier; also resets band flags for the next graph replay.
// ---------------------------------------------------------------------------
__global__ void final_kernel(const float* __restrict__ Wcls,
                             const float* __restrict__ bcls,
                             float* __restrict__ out)
{
    __shared__ float r0[512], r1[512];
    const int b = blockIdx.x, l = threadIdx.x;

    // reset flags (both blocks cover 625 entries; idempotent)
    for (int i = l; i < NBAND; i += 512) g_bflag[i] = 0;

    float U = 0.f;
    for (int c = 0; c < NCHUNK; c++)
        U += g_Upart[(size_t)(b * NCHUNK + c) * LDIM + l];
    float Z = 0.f;
    for (int c = 0; c < NCHUNK; c++) Z += g_Zpart[b * NCHUNK + c];
    const float p = U / Z;
    r0[l] = p * Wcls[l * 2 + 0];
    r1[l] = p * Wcls[l * 2 + 1];
    __syncthreads();
    for (int o = 256; o > 0; o >>= 1) {
        if (l < o) { r0[l] += r0[l + o]; r1[l] += r1[l + o]; }
        __syncthreads();
    }
    if (l == 0) {
        out[b * 2 + 0] = r0[0] + bcls[0];
        out[b * 2 + 1] = r1[0] + bcls[1];
    }
}

// ---------------------------------------------------------------------------
extern "C" void kernel_launch(void* const* d_in, const int* in_sizes, int n_in,
                              void* d_out, int out_size)
{
    const float* x    = (const float*)d_in[0];
    const float* Wf   = (const float*)d_in[1];
    const float* bf   = (const float*)d_in[2];
    const float* Wa   = (const float*)d_in[3];
    const float* ba   = (const float*)d_in[4];
    const float* Wb   = (const float*)d_in[5];
    const float* bb   = (const float*)d_in[6];
    const float* Wc   = (const float*)d_in[7];
    const float* bc   = (const float*)d_in[8];
    const float* Wcls = (const float*)d_in[9];
    const float* bcls = (const float*)d_in[10];
    float* out = (float*)d_out;

    cudaFuncSetAttribute(gemm1_mma, cudaFuncAttributeMaxDynamicSharedMemorySize, G1_SMEM);
    cudaFuncSetAttribute(gemm2_mma, cudaFuncAttributeMaxDynamicSharedMemorySize, G2_SMEM);

    prep_w<<<2048, 256>>>(Wf, Wa, Wb);

    dim3 g1(LDIM / 128, MTOT / 128);           // (4, 625)
    gemm1_mma<<<g1, 256, G1_SMEM>>>(x, bf);

    dim3 g2(DDIM / 64, MTOT / 128);            // (6, 625)
    gemm2_mma<<<g2, 256, G2_SMEM>>>(ba, bb, Wc);

    dim3 g3(NCHUNK, NBATCH);
    pool_kernel<<<g3, 256>>>(bc);
    final_kernel<<<NBATCH, 512>>>(Wcls, bcls, out);
}

// round 15
// speedup vs baseline: 1.1293x; 1.1293x over previous
#include <cuda_runtime.h>
#include <cuda_fp16.h>
#include <math.h>
#include <stdint.h>

// Problem constants
#define MTOT   80000
#define NBATCH 2
#define NPB    40000
#define DIN    1024
#define LDIM   512
#define DDIM   384
#define NDT    6
#define NCHUNK 313      // ceil(40000/128) pool chunks of 128 rows

// Scratch (device globals)
__device__ __align__(16) __half g_xh[(size_t)MTOT * DIN];   // x fp16 (rne)
__device__ __align__(16) __half g_hh[(size_t)MTOT * LDIM];  // h fp16 (gemm2 A + pool)
__device__ __align__(16) __half g_Wfh[LDIM * DIN];          // Wf^T [n][k] fp16
__device__ __align__(16) __half g_Wah[DDIM * LDIM];         // Wa^T [d][k] fp16
__device__ __align__(16) __half g_Wbh[DDIM * LDIM];         // Wb^T [d][k] fp16
__device__ float g_spart[(size_t)NDT * MTOT];
__device__ __align__(16) float g_Upart[(size_t)NBATCH * NCHUNK * LDIM];
__device__ float g_Zpart[NBATCH * NCHUNK];

// ---------------------------------------------------------------------------
// Helpers
// ---------------------------------------------------------------------------
__device__ __forceinline__ uint32_t smem_u32(const void* p) {
    uint32_t a;
    asm("{ .reg .u64 t; cvta.to.shared.u64 t, %1; cvt.u32.u64 %0, t; }"
        : "=r"(a) : "l"(p));
    return a;
}
__device__ __forceinline__ void cp16(uint32_t dst, const void* src) {
    asm volatile("cp.async.cg.shared.global [%0], [%1], 16;" :: "r"(dst), "l"(src));
}
#define CP_COMMIT() asm volatile("cp.async.commit_group;")
#define CP_WAIT1()  asm volatile("cp.async.wait_group 1;")

__device__ __forceinline__ void ldsm4(uint32_t* r, uint32_t addr) {
    asm volatile("ldmatrix.sync.aligned.m8n8.x4.shared.b16 {%0,%1,%2,%3}, [%4];"
                 : "=r"(r[0]), "=r"(r[1]), "=r"(r[2]), "=r"(r[3]) : "r"(addr));
}
__device__ __forceinline__ void mma16(float* c, const uint32_t* a,
                                      uint32_t b0, uint32_t b1) {
    asm volatile(
        "mma.sync.aligned.m16n8k16.row.col.f32.f16.f16.f32 "
        "{%0,%1,%2,%3},{%4,%5,%6,%7},{%8,%9},{%0,%1,%2,%3};"
        : "+f"(c[0]), "+f"(c[1]), "+f"(c[2]), "+f"(c[3])
        : "r"(a[0]), "r"(a[1]), "r"(a[2]), "r"(a[3]), "r"(b0), "r"(b1));
}
__device__ __forceinline__ float tanh_fast(float x) {
    float r;
    asm("tanh.approx.f32 %0, %1;" : "=f"(r) : "f"(x));
    return r;
}
__device__ __forceinline__ float sigmoid_fast(float x) {
    float e, r;
    asm("ex2.approx.f32 %0, %1;" : "=f"(e) : "f"(-x * 1.4426950408889634f));
    asm("rcp.approx.f32 %0, %1;" : "=f"(r) : "f"(1.0f + e));
    return r;
}

// ---------------------------------------------------------------------------
// Pre-passes: fp16(rne) conversions
// ---------------------------------------------------------------------------
__global__ void prep_x(const float* __restrict__ x)
{
    const size_t tot = (size_t)MTOT * DIN / 8;   // units of 8 floats
    size_t i = (size_t)blockIdx.x * 256 + threadIdx.x;
    const size_t step = (size_t)gridDim.x * 256;
    for (; i < tot; i += step) {
        float4 v0 = ((const float4*)x)[2 * i];
        float4 v1 = ((const float4*)x)[2 * i + 1];
        __half2 h0 = __floats2half2_rn(v0.x, v0.y);
        __half2 h1 = __floats2half2_rn(v0.z, v0.w);
        __half2 h2 = __floats2half2_rn(v1.x, v1.y);
        __half2 h3 = __floats2half2_rn(v1.z, v1.w);
        uint4 u;
        u.x = *(uint32_t*)&h0; u.y = *(uint32_t*)&h1;
        u.z = *(uint32_t*)&h2; u.w = *(uint32_t*)&h3;
        ((uint4*)g_xh)[i] = u;
    }
}

__global__ void prep_w(const float* __restrict__ Wf,
                       const float* __restrict__ Wa,
                       const float* __restrict__ Wb)
{
    int idx = blockIdx.x * 256 + threadIdx.x;
    if (idx < LDIM * DIN) {
        int n = idx >> 10, k = idx & 1023;
        g_Wfh[idx] = __float2half_rn(Wf[k * LDIM + n]);
    }
    if (idx < DDIM * LDIM) {
        int d = idx >> 9, k = idx & 511;
        g_Wah[idx] = __float2half_rn(Wa[k * DDIM + d]);
        g_Wbh[idx] = __float2half_rn(Wb[k * DDIM + d]);
    }
}

// ---------------------------------------------------------------------------
// GEMM1 (fp16 mma m16n8k16): h = relu(x @ Wf + bf). CTA 128x128, k-stage 64,
// 3-stage cp.async ring. 8 warps (2m x 4n), warp tile 64x32.
// smem rows 64 fp16 = 128B padded to 144B (conflict-free ldmatrix).
// (R10/R13 winner config, byte-identical)
// ---------------------------------------------------------------------------
#define G1_BOFF  18432
#define G1_STAGE 36864
#define G1_SMEM  (3 * G1_STAGE)

__global__ void __launch_bounds__(256, 2) gemm1_mma(const float* __restrict__ bfp)
{
    extern __shared__ char smch[];
    const uint32_t sb = smem_u32(smch);
    const int tid  = threadIdx.x;
    const int warp = tid >> 5, lane = tid & 31;
    const int gr = lane >> 2, tg = lane & 3;
    const int n0 = blockIdx.x * 128;
    const int m0 = blockIdx.y * 128;
    const int wm = (warp >> 2) * 64, wn = (warp & 3) * 32;

    const uint32_t laneA = (uint32_t)(((lane & 7) + ((lane >> 3) & 1) * 8) * 144
                                      + ((lane >> 4) & 1) * 16);
    const uint32_t laneB = (uint32_t)(((lane & 7) + ((lane >> 4) & 1) * 8) * 144
                                      + ((lane >> 3) & 1) * 16);

    auto issue = [&](int ks, int st) {
        const uint32_t base = sb + st * G1_STAGE;
#pragma unroll
        for (int i = 0; i < 4; i++) {
            int idx = tid + i * 256;
            int row = idx >> 3, c8 = idx & 7;
            cp16(base + row * 144 + c8 * 16,
                 g_xh + (size_t)(m0 + row) * DIN + ks * 64 + c8 * 8);
        }
#pragma unroll
        for (int i = 0; i < 4; i++) {
            int idx = tid + i * 256;
            int row = idx >> 3, c8 = idx & 7;
            cp16(base + G1_BOFF + row * 144 + c8 * 16,
                 g_Wfh + (size_t)(n0 + row) * DIN + ks * 64 + c8 * 8);
        }
    };

    float acc[4][4][4];
#pragma unroll
    for (int a = 0; a < 4; a++)
#pragma unroll
        for (int b = 0; b < 4; b++)
#pragma unroll
            for (int c = 0; c < 4; c++) acc[a][b][c] = 0.f;

    issue(0, 0); CP_COMMIT();
    issue(1, 1); CP_COMMIT();

    for (int ks = 0; ks < 16; ks++) {
        CP_WAIT1();
        __syncthreads();
        if (ks + 2 < 16) issue(ks + 2, (ks + 2) % 3);
        CP_COMMIT();
        const uint32_t sA = sb + (ks % 3) * G1_STAGE;
        const uint32_t sB = sA + G1_BOFF;
#pragma unroll
        for (int kk = 0; kk < 4; kk++) {
            const uint32_t ko = kk * 32;   // 16 fp16 = 32 B
            uint32_t af[4][4];
#pragma unroll
            for (int mf = 0; mf < 4; mf++)
                ldsm4(af[mf], sA + (wm + mf * 16) * 144 + ko + laneA);
            uint32_t bf[2][4];
#pragma unroll
            for (int p = 0; p < 2; p++)
                ldsm4(bf[p], sB + (wn + p * 16) * 144 + ko + laneB);
#pragma unroll
            for (int mf = 0; mf < 4; mf++)
#pragma unroll
                for (int nf = 0; nf < 4; nf++) {
                    const int p = nf >> 1;
                    mma16(acc[mf][nf], af[mf],
                          bf[p][(nf & 1) * 2], bf[p][(nf & 1) * 2 + 1]);
                }
        }
    }

    // Epilogue: bias + relu, store fp16 only
#pragma unroll
    for (int mf = 0; mf < 4; mf++) {
        const int r0 = m0 + wm + mf * 16 + gr;
#pragma unroll
        for (int nf = 0; nf < 4; nf++) {
            const int n = n0 + wn + nf * 8 + 2 * tg;
            const float b0v = bfp[n], b1v = bfp[n + 1];
            ((__half2*)g_hh)[((size_t)r0 * LDIM + n) >> 1] =
                __floats2half2_rn(fmaxf(acc[mf][nf][0] + b0v, 0.f),
                                  fmaxf(acc[mf][nf][1] + b1v, 0.f));
            ((__half2*)g_hh)[((size_t)(r0 + 8) * LDIM + n) >> 1] =
                __floats2half2_rn(fmaxf(acc[mf][nf][2] + b0v, 0.f),
                                  fmaxf(acc[mf][nf][3] + b1v, 0.f));
        }
    }
}

// ---------------------------------------------------------------------------
// GEMM2 (fp16, fused): per (d-tile 64, m-tile 128): acca = h@Wa, accg = h@Wb,
// spart[row] = sum_d tanh(acca+ba)*sigmoid(accg+bb)*wc.
// 8 warps (4m x 2d), warp tile 32m x 32d, dual accumulators. k-stage 64.
// (R9/R13 winner config, byte-identical)
// ---------------------------------------------------------------------------
#define G2_BAOFF 18432
#define G2_BBOFF 27648
#define G2_STAGE 36864
#define G2_SMEM  (3 * G2_STAGE)

__global__ void __launch_bounds__(256, 2) gemm2_mma(
    const float* __restrict__ ba, const float* __restrict__ bb,
    const float* __restrict__ Wc)
{
    extern __shared__ char smch[];
    __shared__ float red[256];
    const uint32_t sb = smem_u32(smch);
    const int tid  = threadIdx.x;
    const int warp = tid >> 5, lane = tid & 31;
    const int gr = lane >> 2, tg = lane & 3;
    const int n0 = blockIdx.x * 64;
    const int m0 = blockIdx.y * 128;
    const int wm = (warp >> 1) * 32;   // m quarter
    const int wd = (warp & 1) * 32;    // d half

    const uint32_t laneA = (uint32_t)(((lane & 7) + ((lane >> 3) & 1) * 8) * 144
                                      + ((lane >> 4) & 1) * 16);
    const uint32_t laneB = (uint32_t)(((lane & 7) + ((lane >> 4) & 1) * 8) * 144
                                      + ((lane >> 3) & 1) * 16);

    auto issue = [&](int ks, int st) {
        const uint32_t base = sb + st * G2_STAGE;
#pragma unroll
        for (int i = 0; i < 4; i++) {
            int idx = tid + i * 256;
            int row = idx >> 3, c8 = idx & 7;
            cp16(base + row * 144 + c8 * 16,
                 g_hh + (size_t)(m0 + row) * LDIM + ks * 64 + c8 * 8);
        }
#pragma unroll
        for (int i = 0; i < 2; i++) {
            int idx = tid + i * 256;
            int row = idx >> 3, c8 = idx & 7;
            cp16(base + G2_BAOFF + row * 144 + c8 * 16,
                 g_Wah + (size_t)(n0 + row) * LDIM + ks * 64 + c8 * 8);
        }
#pragma unroll
        for (int i = 0; i < 2; i++) {
            int idx = tid + i * 256;
            int row = idx >> 3, c8 = idx & 7;
            cp16(base + G2_BBOFF + row * 144 + c8 * 16,
                 g_Wbh + (size_t)(n0 + row) * LDIM + ks * 64 + c8 * 8);
        }
    };

    float acca[2][4][4], accg[2][4][4];
#pragma unroll
    for (int a = 0; a < 2; a++)
#pragma unroll
        for (int b = 0; b < 4; b++)
#pragma unroll
            for (int c = 0; c < 4; c++) { acca[a][b][c] = 0.f; accg[a][b][c] = 0.f; }

    issue(0, 0); CP_COMMIT();
    issue(1, 1); CP_COMMIT();

    for (int ks = 0; ks < 8; ks++) {
        CP_WAIT1();
        __syncthreads();
        if (ks + 2 < 8) issue(ks + 2, (ks + 2) % 3);
        CP_COMMIT();
        const uint32_t sA  = sb + (ks % 3) * G2_STAGE;
        const uint32_t sBa = sA + G2_BAOFF;
        const uint32_t sBb = sA + G2_BBOFF;
#pragma unroll
        for (int kk = 0; kk < 4; kk++) {
            const uint32_t ko = kk * 32;
            uint32_t af[2][4];
#pragma unroll
            for (int mf = 0; mf < 2; mf++)
                ldsm4(af[mf], sA + (wm + mf * 16) * 144 + ko + laneA);
            uint32_t bfa[2][4], bfb[2][4];
#pragma unroll
            for (int p = 0; p < 2; p++) {
                ldsm4(bfa[p], sBa + (wd + p * 16) * 144 + ko + laneB);
                ldsm4(bfb[p], sBb + (wd + p * 16) * 144 + ko + laneB);
            }
#pragma unroll
            for (int mf = 0; mf < 2; mf++)
#pragma unroll
                for (int nf = 0; nf < 4; nf++) {
                    const int p = nf >> 1;
                    mma16(acca[mf][nf], af[mf],
                          bfa[p][(nf & 1) * 2], bfa[p][(nf & 1) * 2 + 1]);
                    mma16(accg[mf][nf], af[mf],
                          bfb[p][(nf & 1) * 2], bfb[p][(nf & 1) * 2 + 1]);
                }
        }
    }

    // Epilogue: tanh*sigmoid*wc, warp-local reduce over its 32 d-cols
    float bav[4][2], bbv[4][2], wcv[4][2];
#pragma unroll
    for (int nf = 0; nf < 4; nf++) {
        const int d = n0 + wd + nf * 8 + 2 * tg;
        bav[nf][0] = ba[d]; bav[nf][1] = ba[d + 1];
        bbv[nf][0] = bb[d]; bbv[nf][1] = bb[d + 1];
        wcv[nf][0] = Wc[d]; wcv[nf][1] = Wc[d + 1];
    }
#pragma unroll
    for (int mf = 0; mf < 2; mf++) {
#pragma unroll
        for (int rh = 0; rh < 2; rh++) {
            float s = 0.f;
#pragma unroll
            for (int nf = 0; nf < 4; nf++) {
#pragma unroll
                for (int c = 0; c < 2; c++) {
                    const float av = tanh_fast(acca[mf][nf][rh * 2 + c] + bav[nf][c]);
                    const float gv = sigmoid_fast(accg[mf][nf][rh * 2 + c] + bbv[nf][c]);
                    s = fmaf(av * gv, wcv[nf][c], s);
                }
            }
            s += __shfl_xor_sync(0xFFFFFFFF, s, 1);
            s += __shfl_xor_sync(0xFFFFFFFF, s, 2);
            if (tg == 0)
                red[(warp & 1) * 128 + wm + mf * 16 + rh * 8 + gr] = s;
        }
    }
    __syncthreads();
    if (tid < 128)
        g_spart[(size_t)blockIdx.x * MTOT + m0 + tid] = red[tid] + red[128 + tid];
}

// ---------------------------------------------------------------------------
// Pool (fused scores): e = exp(bc + sum spart)  [no max pass: |s| <= sum|wc|
// ~ 17, exp safe in fp32];  Upart[l] = sum_n e_n * h[n][l];  Zpart = sum e.
// Chunks of 128 rows -> grid 626 CTAs (was 314) for DRAM parallelism.
// ---------------------------------------------------------------------------
__global__ void __launch_bounds__(256) pool_kernel(const float* __restrict__ bc)
{
    __shared__ float esh[128];
    __shared__ float zr[128];
    const int b = blockIdx.y, cx = blockIdx.x, tid = threadIdx.x;
    const int base = cx * 128;
    if (tid < 128) {
        const int n = base + tid;
        float e = 0.f;
        if (n < NPB) {
            const int gm = b * NPB + n;
            float s = bc[0];
#pragma unroll
            for (int t = 0; t < NDT; t++) s += g_spart[(size_t)t * MTOT + gm];
            e = expf(s);
        }
        esh[tid] = e;
        zr[tid]  = e;
    }
    __syncthreads();
    for (int o = 64; o > 0; o >>= 1) {
        if (tid < o) zr[tid] += zr[tid + o];
        __syncthreads();
    }
    if (tid == 0) g_Zpart[b * NCHUNK + cx] = zr[0];

    const int rmax = min(128, NPB - base);
    const int c = tid * 2;
    const __half* hb = g_hh + ((size_t)b * NPB + base) * LDIM + c;
    float ax = 0.f, ay = 0.f;
    for (int r = 0; r < rmax; r++) {
        const float w = esh[r];
        float2 hv = __half22float2(*(const __half2*)(hb + (size_t)r * LDIM));
        ax = fmaf(w, hv.x, ax);
        ay = fmaf(w, hv.y, ay);
    }
    float* up = g_Upart + (size_t)(b * NCHUNK + cx) * LDIM + c;
    up[0] = ax;
    up[1] = ay;
}

// ---------------------------------------------------------------------------
// Final reduce + classifier
// ---------------------------------------------------------------------------
__global__ void final_kernel(const float* __restrict__ Wcls,
                             const float* __restrict__ bcls,
                             float* __restrict__ out)
{
    __shared__ float r0[512], r1[512];
    const int b = blockIdx.x, l = threadIdx.x;
    float U = 0.f;
    for (int c = 0; c < NCHUNK; c++)
        U += g_Upart[(size_t)(b * NCHUNK + c) * LDIM + l];
    float Z = 0.f;
    for (int c = 0; c < NCHUNK; c++) Z += g_Zpart[b * NCHUNK + c];
    const float p = U / Z;
    r0[l] = p * Wcls[l * 2 + 0];
    r1[l] = p * Wcls[l * 2 + 1];
    __syncthreads();
    for (int o = 256; o > 0; o >>= 1) {
        if (l < o) { r0[l] += r0[l + o]; r1[l] += r1[l + o]; }
        __syncthreads();
    }
    if (l == 0) {
        out[b * 2 + 0] = r0[0] + bcls[0];
        out[b * 2 + 1] = r1[0] + bcls[1];
    }
}

// ---------------------------------------------------------------------------
extern "C" void kernel_launch(void* const* d_in, const int* in_sizes, int n_in,
                              void* d_out, int out_size)
{
    const float* x    = (const float*)d_in[0];
    const float* Wf   = (const float*)d_in[1];
    const float* bf   = (const float*)d_in[2];
    const float* Wa   = (const float*)d_in[3];
    const float* ba   = (const float*)d_in[4];
    const float* Wb   = (const float*)d_in[5];
    const float* bb   = (const float*)d_in[6];
    const float* Wc   = (const float*)d_in[7];
    const float* bc   = (const float*)d_in[8];
    const float* Wcls = (const float*)d_in[9];
    const float* bcls = (const float*)d_in[10];
    float* out = (float*)d_out;

    cudaFuncSetAttribute(gemm1_mma, cudaFuncAttributeMaxDynamicSharedMemorySize, G1_SMEM);
    cudaFuncSetAttribute(gemm2_mma, cudaFuncAttributeMaxDynamicSharedMemorySize, G2_SMEM);

    prep_x<<<2500, 256>>>(x);
    prep_w<<<2048, 256>>>(Wf, Wa, Wb);

    dim3 g1(LDIM / 128, MTOT / 128);           // (4, 625)
    gemm1_mma<<<g1, 256, G1_SMEM>>>(bf);

    dim3 g2(DDIM / 64, MTOT / 128);            // (6, 625)
    gemm2_mma<<<g2, 256, G2_SMEM>>>(ba, bb, Wc);

    dim3 g3(NCHUNK, NBATCH);                   // (313, 2)
    pool_kernel<<<g3, 256>>>(bc);
    final_kernel<<<NBATCH, 512>>>(Wcls, bcls, out);
}

// round 16
// speedup vs baseline: 1.1480x; 1.0166x over previous
#include <cuda_runtime.h>
#include <cuda_fp16.h>
#include <math.h>
#include <stdint.h>

// Problem constants
#define MTOT   80000
#define NBATCH 2
#define NPB    40000
#define DIN    1024
#define LDIM   512
#define DDIM   384
#define NDT    6
#define NCHUNK 313      // ceil(40000/128) pool chunks of 128 rows
#define NBAND  625
#define G1_CTAS 2500    // 4 x 625

// Scratch (device globals)
__device__ __align__(16) __half g_xh[(size_t)MTOT * DIN];   // x fp16 (rne)
__device__ __align__(16) __half g_hh[(size_t)MTOT * LDIM];  // h fp16 (gemm2 A + pool)
__device__ __align__(16) __half g_Wfh[LDIM * DIN];          // Wf^T [n][k] fp16
__device__ __align__(16) __half g_Wah[DDIM * LDIM];         // Wa^T [d][k] fp16
__device__ __align__(16) __half g_Wbh[DDIM * LDIM];         // Wb^T [d][k] fp16
__device__ float g_spart[(size_t)NDT * MTOT];
__device__ __align__(16) float g_Upart[(size_t)NBATCH * NCHUNK * LDIM];
__device__ float g_Zpart[NBATCH * NCHUNK];
__device__ int g_cnt[NBAND];    // per-band gemm1-CTA completion counters

// ---------------------------------------------------------------------------
// Helpers
// ---------------------------------------------------------------------------
__device__ __forceinline__ uint32_t smem_u32(const void* p) {
    uint32_t a;
    asm("{ .reg .u64 t; cvta.to.shared.u64 t, %1; cvt.u32.u64 %0, t; }"
        : "=r"(a) : "l"(p));
    return a;
}
__device__ __forceinline__ void cp16(uint32_t dst, const void* src) {
    asm volatile("cp.async.cg.shared.global [%0], [%1], 16;" :: "r"(dst), "l"(src));
}
#define CP_COMMIT() asm volatile("cp.async.commit_group;")
#define CP_WAIT1()  asm volatile("cp.async.wait_group 1;")

__device__ __forceinline__ void ldsm4(uint32_t* r, uint32_t addr) {
    asm volatile("ldmatrix.sync.aligned.m8n8.x4.shared.b16 {%0,%1,%2,%3}, [%4];"
                 : "=r"(r[0]), "=r"(r[1]), "=r"(r[2]), "=r"(r[3]) : "r"(addr));
}
__device__ __forceinline__ void mma16(float* c, const uint32_t* a,
                                      uint32_t b0, uint32_t b1) {
    asm volatile(
        "mma.sync.aligned.m16n8k16.row.col.f32.f16.f16.f32 "
        "{%0,%1,%2,%3},{%4,%5,%6,%7},{%8,%9},{%0,%1,%2,%3};"
        : "+f"(c[0]), "+f"(c[1]), "+f"(c[2]), "+f"(c[3])
        : "r"(a[0]), "r"(a[1]), "r"(a[2]), "r"(a[3]), "r"(b0), "r"(b1));
}
__device__ __forceinline__ float tanh_fast(float x) {
    float r;
    asm("tanh.approx.f32 %0, %1;" : "=f"(r) : "f"(x));
    return r;
}
__device__ __forceinline__ float sigmoid_fast(float x) {
    float e, r;
    asm("ex2.approx.f32 %0, %1;" : "=f"(e) : "f"(-x * 1.4426950408889634f));
    asm("rcp.approx.f32 %0, %1;" : "=f"(r) : "f"(1.0f + e));
    return r;
}

// ---------------------------------------------------------------------------
// Pre-passes
// ---------------------------------------------------------------------------
__global__ void prep_x(const float* __restrict__ x)
{
    const size_t tot = (size_t)MTOT * DIN / 8;
    size_t i = (size_t)blockIdx.x * 256 + threadIdx.x;
    const size_t step = (size_t)gridDim.x * 256;
    for (; i < tot; i += step) {
        float4 v0 = ((const float4*)x)[2 * i];
        float4 v1 = ((const float4*)x)[2 * i + 1];
        __half2 h0 = __floats2half2_rn(v0.x, v0.y);
        __half2 h1 = __floats2half2_rn(v0.z, v0.w);
        __half2 h2 = __floats2half2_rn(v1.x, v1.y);
        __half2 h3 = __floats2half2_rn(v1.z, v1.w);
        uint4 u;
        u.x = *(uint32_t*)&h0; u.y = *(uint32_t*)&h1;
        u.z = *(uint32_t*)&h2; u.w = *(uint32_t*)&h3;
        ((uint4*)g_xh)[i] = u;
    }
}

__global__ void prep_w(const float* __restrict__ Wf,
                       const float* __restrict__ Wa,
                       const float* __restrict__ Wb)
{
    int idx = blockIdx.x * 256 + threadIdx.x;
    if (idx < NBAND) g_cnt[idx] = 0;     // reset band counters for this run
    if (idx < LDIM * DIN) {
        int n = idx >> 10, k = idx & 1023;
        g_Wfh[idx] = __float2half_rn(Wf[k * LDIM + n]);
    }
    if (idx < DDIM * LDIM) {
        int d = idx >> 9, k = idx & 511;
        g_Wah[idx] = __float2half_rn(Wa[k * DDIM + d]);
        g_Wbh[idx] = __float2half_rn(Wb[k * DDIM + d]);
    }
}

// ---------------------------------------------------------------------------
// FUSED GEMM kernel. 1D grid of 6250 CTAs:
//   bid < 2500 : gemm1 branch (bx=bid&3, band=bid>>2)  — R10/R13 mainloop
//   bid >= 2500: gemm2 branch (dt=r%6, band=r/6)       — R9/R13 mainloop,
//                spins until the band's 4 gemm1 CTAs have published h.
// Deadlock-free under monotonic bid dispatch: a resident gemm2 CTA implies
// all (earlier) gemm1 bids are dispatched; gemm1 CTAs never wait.
// ---------------------------------------------------------------------------
#define G_BOFF   18432
#define G2_BAOFF 18432
#define G2_BBOFF 27648
#define G_STAGE  36864
#define G_SMEM   (3 * G_STAGE)

__global__ void __launch_bounds__(256, 2) gemm_fused(
    const float* __restrict__ bfp,
    const float* __restrict__ ba, const float* __restrict__ bb,
    const float* __restrict__ Wc)
{
    extern __shared__ char smch[];
    __shared__ float red[256];
    const uint32_t sb = smem_u32(smch);
    const int tid  = threadIdx.x;
    const int warp = tid >> 5, lane = tid & 31;
    const int gr = lane >> 2, tg = lane & 3;
    const int bid = blockIdx.x;

    const uint32_t laneA = (uint32_t)(((lane & 7) + ((lane >> 3) & 1) * 8) * 144
                                      + ((lane >> 4) & 1) * 16);
    const uint32_t laneB = (uint32_t)(((lane & 7) + ((lane >> 4) & 1) * 8) * 144
                                      + ((lane >> 3) & 1) * 16);

    if (bid < G1_CTAS) {
        // ================= GEMM1 branch =================
        const int n0 = (bid & 3) * 128;
        const int band = bid >> 2;
        const int m0 = band * 128;
        const int wm = (warp >> 2) * 64, wn = (warp & 3) * 32;

        auto issue = [&](int ks, int st) {
            const uint32_t base = sb + st * G_STAGE;
#pragma unroll
            for (int i = 0; i < 4; i++) {
                int idx = tid + i * 256;
                int row = idx >> 3, c8 = idx & 7;
                cp16(base + row * 144 + c8 * 16,
                     g_xh + (size_t)(m0 + row) * DIN + ks * 64 + c8 * 8);
            }
#pragma unroll
            for (int i = 0; i < 4; i++) {
                int idx = tid + i * 256;
                int row = idx >> 3, c8 = idx & 7;
                cp16(base + G_BOFF + row * 144 + c8 * 16,
                     g_Wfh + (size_t)(n0 + row) * DIN + ks * 64 + c8 * 8);
            }
        };

        float acc[4][4][4];
#pragma unroll
        for (int a = 0; a < 4; a++)
#pragma unroll
            for (int b = 0; b < 4; b++)
#pragma unroll
                for (int c = 0; c < 4; c++) acc[a][b][c] = 0.f;

        issue(0, 0); CP_COMMIT();
        issue(1, 1); CP_COMMIT();

        for (int ks = 0; ks < 16; ks++) {
            CP_WAIT1();
            __syncthreads();
            if (ks + 2 < 16) issue(ks + 2, (ks + 2) % 3);
            CP_COMMIT();
            const uint32_t sA = sb + (ks % 3) * G_STAGE;
            const uint32_t sB = sA + G_BOFF;
#pragma unroll
            for (int kk = 0; kk < 4; kk++) {
                const uint32_t ko = kk * 32;
                uint32_t af[4][4];
#pragma unroll
                for (int mf = 0; mf < 4; mf++)
                    ldsm4(af[mf], sA + (wm + mf * 16) * 144 + ko + laneA);
                uint32_t bf[2][4];
#pragma unroll
                for (int p = 0; p < 2; p++)
                    ldsm4(bf[p], sB + (wn + p * 16) * 144 + ko + laneB);
#pragma unroll
                for (int mf = 0; mf < 4; mf++)
#pragma unroll
                    for (int nf = 0; nf < 4; nf++) {
                        const int p = nf >> 1;
                        mma16(acc[mf][nf], af[mf],
                              bf[p][(nf & 1) * 2], bf[p][(nf & 1) * 2 + 1]);
                    }
            }
        }

        // Epilogue: bias + relu, store fp16; then publish band completion
#pragma unroll
        for (int mf = 0; mf < 4; mf++) {
            const int r0 = m0 + wm + mf * 16 + gr;
#pragma unroll
            for (int nf = 0; nf < 4; nf++) {
                const int n = n0 + wn + nf * 8 + 2 * tg;
                const float b0v = bfp[n], b1v = bfp[n + 1];
                ((__half2*)g_hh)[((size_t)r0 * LDIM + n) >> 1] =
                    __floats2half2_rn(fmaxf(acc[mf][nf][0] + b0v, 0.f),
                                      fmaxf(acc[mf][nf][1] + b1v, 0.f));
                ((__half2*)g_hh)[((size_t)(r0 + 8) * LDIM + n) >> 1] =
                    __floats2half2_rn(fmaxf(acc[mf][nf][2] + b0v, 0.f),
                                      fmaxf(acc[mf][nf][3] + b1v, 0.f));
            }
        }
        __syncthreads();
        if (tid == 0) {
            __threadfence();
            atomicAdd(&g_cnt[band], 1);
        }
    } else {
        // ================= GEMM2 branch =================
        const int r = bid - G1_CTAS;
        const int dt = r % 6;
        const int band = r / 6;
        const int n0 = dt * 64;
        const int m0 = band * 128;
        const int wm = (warp >> 1) * 32;
        const int wd = (warp & 1) * 32;

        // wait for this band's h
        if (tid == 0) {
            while (((volatile int*)g_cnt)[band] < 4) __nanosleep(128);
            __threadfence();
        }
        __syncthreads();

        auto issue = [&](int ks, int st) {
            const uint32_t base = sb + st * G_STAGE;
#pragma unroll
            for (int i = 0; i < 4; i++) {
                int idx = tid + i * 256;
                int row = idx >> 3, c8 = idx & 7;
                cp16(base + row * 144 + c8 * 16,
                     g_hh + (size_t)(m0 + row) * LDIM + ks * 64 + c8 * 8);
            }
#pragma unroll
            for (int i = 0; i < 2; i++) {
                int idx = tid + i * 256;
                int row = idx >> 3, c8 = idx & 7;
                cp16(base + G2_BAOFF + row * 144 + c8 * 16,
                     g_Wah + (size_t)(n0 + row) * LDIM + ks * 64 + c8 * 8);
            }
#pragma unroll
            for (int i = 0; i < 2; i++) {
                int idx = tid + i * 256;
                int row = idx >> 3, c8 = idx & 7;
                cp16(base + G2_BBOFF + row * 144 + c8 * 16,
                     g_Wbh + (size_t)(n0 + row) * LDIM + ks * 64 + c8 * 8);
            }
        };

        float acca[2][4][4], accg[2][4][4];
#pragma unroll
        for (int a = 0; a < 2; a++)
#pragma unroll
            for (int b = 0; b < 4; b++)
#pragma unroll
                for (int c = 0; c < 4; c++) { acca[a][b][c] = 0.f; accg[a][b][c] = 0.f; }

        issue(0, 0); CP_COMMIT();
        issue(1, 1); CP_COMMIT();

        for (int ks = 0; ks < 8; ks++) {
            CP_WAIT1();
            __syncthreads();
            if (ks + 2 < 8) issue(ks + 2, (ks + 2) % 3);
            CP_COMMIT();
            const uint32_t sA  = sb + (ks % 3) * G_STAGE;
            const uint32_t sBa = sA + G2_BAOFF;
            const uint32_t sBb = sA + G2_BBOFF;
#pragma unroll
            for (int kk = 0; kk < 4; kk++) {
                const uint32_t ko = kk * 32;
                uint32_t af[2][4];
#pragma unroll
                for (int mf = 0; mf < 2; mf++)
                    ldsm4(af[mf], sA + (wm + mf * 16) * 144 + ko + laneA);
                uint32_t bfa[2][4], bfb[2][4];
#pragma unroll
                for (int p = 0; p < 2; p++) {
                    ldsm4(bfa[p], sBa + (wd + p * 16) * 144 + ko + laneB);
                    ldsm4(bfb[p], sBb + (wd + p * 16) * 144 + ko + laneB);
                }
#pragma unroll
                for (int mf = 0; mf < 2; mf++)
#pragma unroll
                    for (int nf = 0; nf < 4; nf++) {
                        const int p = nf >> 1;
                        mma16(acca[mf][nf], af[mf],
                              bfa[p][(nf & 1) * 2], bfa[p][(nf & 1) * 2 + 1]);
                        mma16(accg[mf][nf], af[mf],
                              bfb[p][(nf & 1) * 2], bfb[p][(nf & 1) * 2 + 1]);
                    }
            }
        }

        // Epilogue: tanh*sigmoid*wc, warp-local reduce
        float bav[4][2], bbv[4][2], wcv[4][2];
#pragma unroll
        for (int nf = 0; nf < 4; nf++) {
            const int d = n0 + wd + nf * 8 + 2 * tg;
            bav[nf][0] = ba[d]; bav[nf][1] = ba[d + 1];
            bbv[nf][0] = bb[d]; bbv[nf][1] = bb[d + 1];
            wcv[nf][0] = Wc[d]; wcv[nf][1] = Wc[d + 1];
        }
#pragma unroll
        for (int mf = 0; mf < 2; mf++) {
#pragma unroll
            for (int rh = 0; rh < 2; rh++) {
                float s = 0.f;
#pragma unroll
                for (int nf = 0; nf < 4; nf++) {
#pragma unroll
                    for (int c = 0; c < 2; c++) {
                        const float av = tanh_fast(acca[mf][nf][rh * 2 + c] + bav[nf][c]);
                        const float gv = sigmoid_fast(accg[mf][nf][rh * 2 + c] + bbv[nf][c]);
                        s = fmaf(av * gv, wcv[nf][c], s);
                    }
                }
                s += __shfl_xor_sync(0xFFFFFFFF, s, 1);
                s += __shfl_xor_sync(0xFFFFFFFF, s, 2);
                if (tg == 0)
                    red[(warp & 1) * 128 + wm + mf * 16 + rh * 8 + gr] = s;
            }
        }
        __syncthreads();
        if (tid < 128)
            g_spart[(size_t)dt * MTOT + m0 + tid] = red[tid] + red[128 + tid];
    }
}

// ---------------------------------------------------------------------------
// Pool (fused scores): e = exp(bc + sum spart); Upart/Zpart partials.
// ---------------------------------------------------------------------------
__global__ void __launch_bounds__(256) pool_kernel(const float* __restrict__ bc)
{
    __shared__ float esh[128];
    __shared__ float zr[128];
    const int b = blockIdx.y, cx = blockIdx.x, tid = threadIdx.x;
    const int base = cx * 128;
    if (tid < 128) {
        const int n = base + tid;
        float e = 0.f;
        if (n < NPB) {
            const int gm = b * NPB + n;
            float s = bc[0];
#pragma unroll
            for (int t = 0; t < NDT; t++) s += g_spart[(size_t)t * MTOT + gm];
            e = expf(s);
        }
        esh[tid] = e;
        zr[tid]  = e;
    }
    __syncthreads();
    for (int o = 64; o > 0; o >>= 1) {
        if (tid < o) zr[tid] += zr[tid + o];
        __syncthreads();
    }
    if (tid == 0) g_Zpart[b * NCHUNK + cx] = zr[0];

    const int rmax = min(128, NPB - base);
    const int c = tid * 2;
    const __half* hb = g_hh + ((size_t)b * NPB + base) * LDIM + c;
    float ax = 0.f, ay = 0.f;
    for (int r = 0; r < rmax; r++) {
        const float w = esh[r];
        float2 hv = __half22float2(*(const __half2*)(hb + (size_t)r * LDIM));
        ax = fmaf(w, hv.x, ax);
        ay = fmaf(w, hv.y, ay);
    }
    float* up = g_Upart + (size_t)(b * NCHUNK + cx) * LDIM + c;
    up[0] = ax;
    up[1] = ay;
}

// ---------------------------------------------------------------------------
// Final reduce + classifier
// ---------------------------------------------------------------------------
__global__ void final_kernel(const float* __restrict__ Wcls,
                             const float* __restrict__ bcls,
                             float* __restrict__ out)
{
    __shared__ float r0[512], r1[512];
    const int b = blockIdx.x, l = threadIdx.x;
    float U = 0.f;
    for (int c = 0; c < NCHUNK; c++)
        U += g_Upart[(size_t)(b * NCHUNK + c) * LDIM + l];
    float Z = 0.f;
    for (int c = 0; c < NCHUNK; c++) Z += g_Zpart[b * NCHUNK + c];
    const float p = U / Z;
    r0[l] = p * Wcls[l * 2 + 0];
    r1[l] = p * Wcls[l * 2 + 1];
    __syncthreads();
    for (int o = 256; o > 0; o >>= 1) {
        if (l < o) { r0[l] += r0[l + o]; r1[l] += r1[l + o]; }
        __syncthreads();
    }
    if (l == 0) {
        out[b * 2 + 0] = r0[0] + bcls[0];
        out[b * 2 + 1] = r1[0] + bcls[1];
    }
}

// ---------------------------------------------------------------------------
extern "C" void kernel_launch(void* const* d_in, const int* in_sizes, int n_in,
                              void* d_out, int out_size)
{
    const float* x    = (const float*)d_in[0];
    const float* Wf   = (const float*)d_in[1];
    const float* bf   = (const float*)d_in[2];
    const float* Wa   = (const float*)d_in[3];
    const float* ba   = (const float*)d_in[4];
    const float* Wb   = (const float*)d_in[5];
    const float* bb   = (const float*)d_in[6];
    const float* Wc   = (const float*)d_in[7];
    const float* bc   = (const float*)d_in[8];
    const float* Wcls = (const float*)d_in[9];
    const float* bcls = (const float*)d_in[10];
    float* out = (float*)d_out;

    cudaFuncSetAttribute(gemm_fused, cudaFuncAttributeMaxDynamicSharedMemorySize, G_SMEM);

    prep_x<<<2500, 256>>>(x);
    prep_w<<<2048, 256>>>(Wf, Wa, Wb);

    gemm_fused<<<G1_CTAS + 6 * NBAND, 256, G_SMEM>>>(bf, ba, bb, Wc);

    dim3 g3(NCHUNK, NBATCH);                   // (313, 2)
    pool_kernel<<<g3, 256>>>(bc);
    final_kernel<<<NBATCH, 512>>>(Wcls, bcls, out);
}